// round 1
// baseline (speedup 1.0000x reference)
#include <cuda_runtime.h>
#include <math.h>

#define B_      32
#define N_      325
#define L_      12
#define D_      128
#define H_      8
#define DK      16
#define BN      (B_*N_)        // 10400
#define ROWS    (BN*L_)        // 124800
#define MAXREL  11
#define LL      (L_*L_)        // 144
#define HLL     (H_*LL)        // 1152

// ---- static device scratch (no runtime allocation allowed) ----
__device__ __align__(16) float g_W[4][D_*D_];      // normalized wq,wk,wv,fc
__device__ __align__(16) float g_K2[LL*DK];
__device__ __align__(16) float g_V2[LL*DK];
__device__ __align__(16) float g_ctx[(size_t)ROWS*D_];   // 64 MB
__device__ __align__(16) float g_psum[D_*BN];
__device__ __align__(16) float g_psumsq[D_*BN];
__device__ float g_scale[D_];
__device__ float g_shift[D_];

// ---------------------------------------------------------------------------
// Kernel 1: weight-norm the 4 matrices + build relative-position tables
// ---------------------------------------------------------------------------
__global__ void prep_kernel(const float* __restrict__ wq_v, const float* __restrict__ wq_g,
                            const float* __restrict__ wk_v, const float* __restrict__ wk_g,
                            const float* __restrict__ wv_v, const float* __restrict__ wv_g,
                            const float* __restrict__ fc_v, const float* __restrict__ fc_g,
                            const float* __restrict__ rel_k, const float* __restrict__ rel_v) {
    int blk = blockIdx.x;
    if (blk < 4) {
        const float* v; const float* g;
        switch (blk) {
            case 0: v = wq_v; g = wq_g; break;
            case 1: v = wk_v; g = wk_g; break;
            case 2: v = wv_v; g = wv_g; break;
            default: v = fc_v; g = fc_g; break;
        }
        int r = threadIdx.x;           // 128 rows, one per thread
        float s = 0.f;
        for (int d = 0; d < D_; d++) { float x = v[r*D_ + d]; s += x*x; }
        float sc = g[r] * rsqrtf(s);
        for (int d = 0; d < D_; d++) g_W[blk][r*D_ + d] = v[r*D_ + d] * sc;
    } else {
        for (int t = threadIdx.x; t < LL; t += blockDim.x) {
            int q = t / L_, k = t % L_;
            int dist = k - q;
            dist = max(-MAXREL, min(MAXREL, dist));
            int row = dist + MAXREL;
            for (int d = 0; d < DK; d++) {
                g_K2[t*DK + d] = rel_k[row*DK + d];
                g_V2[t*DK + d] = rel_v[row*DK + d];
            }
        }
    }
}

// ---------------------------------------------------------------------------
// Kernel 2: fused attention per (b,n). Projections -> scores -> w1 mix ->
// leakyReLU -> softmax -> w2 mix -> dual context -> ctx + BN partials + attn out
// ---------------------------------------------------------------------------
__global__ __launch_bounds__(256) void attn_kernel(const float* __restrict__ inQ,
                                                   const float* __restrict__ inK,
                                                   const float* __restrict__ inV,
                                                   const float* __restrict__ w1,
                                                   const float* __restrict__ w2,
                                                   float* __restrict__ attn_out) {
    __shared__ __align__(16) float s_in[L_*D_];   // input tile, later reused for ctx staging
    __shared__ __align__(16) float s_q[L_*D_];
    __shared__ __align__(16) float s_k[L_*D_];
    __shared__ __align__(16) float s_v[L_*D_];
    __shared__ float s_sc[HLL];
    __shared__ float s_at[HLL];
    __shared__ float s_at2[HLL];
    __shared__ float s_w1[H_*H_], s_w2[H_*H_];

    const int bn  = blockIdx.x;
    const int tid = threadIdx.x;
    const int c    = tid & 127;   // channel 0..127
    const int half = tid >> 7;    // 0 -> rows 0..5, 1 -> rows 6..11

    if (tid < H_*H_) { s_w1[tid] = w1[tid]; s_w2[tid] = w2[tid]; }

    // ---- projections: Q,K,V = X @ W^T ----
    for (int m = 0; m < 3; m++) {
        const float* src = (m == 0 ? inQ : (m == 1 ? inK : inV)) + (size_t)bn * L_ * D_;
        float* dst = (m == 0 ? s_q : (m == 1 ? s_k : s_v));
        for (int i = tid; i < (L_*D_)/4; i += 256)
            ((float4*)s_in)[i] = ((const float4*)src)[i];
        __syncthreads();

        const float4* W4 = (const float4*)(g_W[m] + c * D_);
        float acc[6];
        #pragma unroll
        for (int l = 0; l < 6; l++) acc[l] = 0.f;
        #pragma unroll 8
        for (int d4 = 0; d4 < 32; d4++) {
            float4 w = W4[d4];
            #pragma unroll
            for (int l = 0; l < 6; l++) {
                float4 x = ((const float4*)(s_in + (half*6 + l)*D_))[d4];
                acc[l] += x.x*w.x + x.y*w.y + x.z*w.z + x.w*w.w;
            }
        }
        #pragma unroll
        for (int l = 0; l < 6; l++) dst[(half*6 + l)*D_ + c] = acc[l];
        __syncthreads();
    }

    // ---- scores: s1 (QK^T per head) + s2 (rel-pos keys), scaled ----
    for (int idx = tid; idx < HLL; idx += 256) {
        int h = idx / LL, rem = idx % LL;
        int i = rem / L_, j = rem % L_;
        const float* qi = s_q + i*D_ + h*DK;
        const float* kj = s_k + j*D_ + h*DK;
        const float* k2 = g_K2 + rem*DK;
        float s = 0.f;
        #pragma unroll
        for (int d = 0; d < DK; d++) s += qi[d] * (kj[d] + k2[d]);
        s_sc[idx] = s * 0.25f;   // 1/sqrt(16)
    }
    __syncthreads();

    // ---- cross-head mix (w1) + leaky relu ----
    for (int idx = tid; idx < HLL; idx += 256) {
        int g = idx / LL, rem = idx % LL;
        float s = 0.f;
        #pragma unroll
        for (int h = 0; h < H_; h++) s += s_sc[h*LL + rem] * s_w1[h*H_ + g];
        s_at[idx] = (s > 0.f) ? s : 0.2f * s;
    }
    __syncthreads();

    // ---- softmax over k (96 rows of length 12) ----
    if (tid < H_*L_) {
        float* row = s_at + tid * L_;
        float mx = row[0];
        #pragma unroll
        for (int j = 1; j < L_; j++) mx = fmaxf(mx, row[j]);
        float sum = 0.f;
        #pragma unroll
        for (int j = 0; j < L_; j++) { float e = __expf(row[j] - mx); row[j] = e; sum += e; }
        float inv = 1.f / sum;
        #pragma unroll
        for (int j = 0; j < L_; j++) row[j] *= inv;
    }
    __syncthreads();

    // ---- cross-head mix (w2) ----
    for (int idx = tid; idx < HLL; idx += 256) {
        int g = idx / LL, rem = idx % LL;
        float s = 0.f;
        #pragma unroll
        for (int h = 0; h < H_; h++) s += s_at[h*LL + rem] * s_w2[h*H_ + g];
        s_at2[idx] = s;
    }
    __syncthreads();

    // ---- attn_ret[q, (bn*H + h), k] ----
    for (int idx = tid; idx < HLL; idx += 256) {
        int h = idx / LL, rem = idx % LL;
        int i = rem / L_, j = rem % L_;
        attn_out[(size_t)i * ((size_t)BN*H_*L_) + ((size_t)bn*H_ + h)*L_ + j] = s_at2[idx];
    }

    // ---- context: c1 (attn @ V) + c2 (attn @ rel-pos V) ----
    const int hh = c >> 4, dd = c & 15;
    float accc[6];
    #pragma unroll
    for (int l = 0; l < 6; l++) accc[l] = 0.f;
    #pragma unroll
    for (int j = 0; j < L_; j++) {
        float vj = s_v[j*D_ + c];
        #pragma unroll
        for (int l = 0; l < 6; l++) {
            int i = half*6 + l;
            accc[l] += s_at2[hh*LL + i*L_ + j] * (vj + g_V2[(i*L_ + j)*DK + dd]);
        }
    }
    float* ctxp = g_ctx + (size_t)bn * L_ * D_;
    #pragma unroll
    for (int l = 0; l < 6; l++) {
        s_in[(half*6 + l)*D_ + c] = accc[l];    // stage for per-channel stats
        ctxp[(half*6 + l)*D_ + c] = accc[l];
    }
    __syncthreads();

    // ---- per-channel BN partial sums (deterministic, no atomics) ----
    if (tid < D_) {
        float s = 0.f, ss = 0.f;
        #pragma unroll
        for (int i = 0; i < L_; i++) { float x = s_in[i*D_ + tid]; s += x; ss += x*x; }
        g_psum[tid*BN + bn]   = s;
        g_psumsq[tid*BN + bn] = ss;
    }
}

// ---------------------------------------------------------------------------
// Kernel 3: finalize BN stats (one block per channel, fixed reduction order)
// ---------------------------------------------------------------------------
__global__ void stats_kernel(const float* __restrict__ gamma, const float* __restrict__ beta) {
    const int c = blockIdx.x;
    __shared__ float sh[256], shq[256];
    float s = 0.f, ss = 0.f;
    for (int t = threadIdx.x; t < BN; t += 256) {
        s  += g_psum[c*BN + t];
        ss += g_psumsq[c*BN + t];
    }
    sh[threadIdx.x] = s; shq[threadIdx.x] = ss;
    __syncthreads();
    for (int st = 128; st > 0; st >>= 1) {
        if (threadIdx.x < st) {
            sh[threadIdx.x]  += sh[threadIdx.x + st];
            shq[threadIdx.x] += shq[threadIdx.x + st];
        }
        __syncthreads();
    }
    if (threadIdx.x == 0) {
        const float invN = 1.f / (float)ROWS;
        float mean = sh[0] * invN;
        float var  = shq[0] * invN - mean*mean;
        float sc = rsqrtf(var + 1e-5f) * gamma[c];
        g_scale[c] = sc;
        g_shift[c] = beta[c] - mean * sc;
    }
}

// ---------------------------------------------------------------------------
// Kernel 4: BN-apply + fc GEMM + ReLU + residual
// ---------------------------------------------------------------------------
__global__ __launch_bounds__(256) void out_kernel(const float* __restrict__ inV,
                                                  float* __restrict__ out) {
    __shared__ __align__(16) float s_x[L_*D_];
    __shared__ float s_scale[D_], s_shift[D_];
    const int bn  = blockIdx.x;
    const int tid = threadIdx.x;
    const int c    = tid & 127;
    const int half = tid >> 7;

    if (tid < D_) { s_scale[tid] = g_scale[tid]; s_shift[tid] = g_shift[tid]; }
    __syncthreads();

    const float* ctxp = g_ctx + (size_t)bn * L_ * D_;
    for (int i = tid; i < L_*D_; i += 256) {
        int cc = i & 127;
        s_x[i] = ctxp[i] * s_scale[cc] + s_shift[cc];
    }
    __syncthreads();

    const float4* W4 = (const float4*)(g_W[3] + c * D_);
    float acc[6];
    #pragma unroll
    for (int l = 0; l < 6; l++) acc[l] = 0.f;
    #pragma unroll 8
    for (int d4 = 0; d4 < 32; d4++) {
        float4 w = W4[d4];
        #pragma unroll
        for (int l = 0; l < 6; l++) {
            float4 x = ((const float4*)(s_x + (half*6 + l)*D_))[d4];
            acc[l] += x.x*w.x + x.y*w.y + x.z*w.z + x.w*w.w;
        }
    }
    const float* vrow = inV + (size_t)bn * L_ * D_;
    float* orow = out + (size_t)bn * L_ * D_;
    #pragma unroll
    for (int l = 0; l < 6; l++) {
        float r = acc[l];
        r = (r > 0.f) ? r : 0.f;
        orow[(half*6 + l)*D_ + c] = r + vrow[(half*6 + l)*D_ + c];
    }
}

// ---------------------------------------------------------------------------
extern "C" void kernel_launch(void* const* d_in, const int* in_sizes, int n_in,
                              void* d_out, int out_size) {
    const float* inQ   = (const float*)d_in[0];
    const float* inK   = (const float*)d_in[1];
    const float* inV   = (const float*)d_in[2];
    const float* wq_v  = (const float*)d_in[3];
    const float* wq_g  = (const float*)d_in[4];
    const float* wk_v  = (const float*)d_in[5];
    const float* wk_g  = (const float*)d_in[6];
    const float* wv_v  = (const float*)d_in[7];
    const float* wv_g  = (const float*)d_in[8];
    const float* fc_v  = (const float*)d_in[9];
    const float* fc_g  = (const float*)d_in[10];
    const float* rel_k = (const float*)d_in[11];
    const float* rel_v = (const float*)d_in[12];
    const float* w1    = (const float*)d_in[13];
    const float* w2    = (const float*)d_in[14];
    const float* gamma = (const float*)d_in[15];
    const float* beta  = (const float*)d_in[16];

    float* out      = (float*)d_out;
    float* attn_out = out + (size_t)ROWS * D_;   // second tuple element

    prep_kernel<<<5, 128>>>(wq_v, wq_g, wk_v, wk_g, wv_v, wv_g, fc_v, fc_g, rel_k, rel_v);
    attn_kernel<<<BN, 256>>>(inQ, inK, inV, w1, w2, attn_out);
    stats_kernel<<<D_, 256>>>(gamma, beta);
    out_kernel<<<BN, 256>>>(inV, out);
}

// round 2
// speedup vs baseline: 1.9790x; 1.9790x over previous
#include <cuda_runtime.h>
#include <math.h>

#define B_      32
#define N_      325
#define L_      12
#define D_      128
#define H_      8
#define DK      16
#define BN      (B_*N_)        // 10400
#define ROWS    (BN*L_)        // 124800
#define MAXREL  11
#define LL      (L_*L_)        // 144
#define HLL     (H_*LL)        // 1152

typedef unsigned long long u64t;

// ---- static device scratch (no runtime allocation allowed) ----
// Packed weights: b64 element [d2][c] = (w[c][2*d2], w[c][2*d2+1]), d2 in [0,64)
__device__ __align__(16) float g_Wkp[4][D_*D_];
__device__ __align__(16) float g_K2[LL*DK];
__device__ __align__(16) float g_V2[LL*DK];
__device__ __align__(16) float g_ctx[(size_t)ROWS*D_];   // 64 MB
__device__ __align__(16) float g_psum[D_*BN];
__device__ __align__(16) float g_psumsq[D_*BN];
__device__ float g_scale[D_];
__device__ float g_shift[D_];

__device__ __forceinline__ u64t fma2(u64t a, u64t b, u64t c) {
    u64t d;
    asm("fma.rn.f32x2 %0, %1, %2, %3;" : "=l"(d) : "l"(a), "l"(b), "l"(c));
    return d;
}
__device__ __forceinline__ float hsum2(u64t v) {
    float lo, hi;
    asm("mov.b64 {%0,%1}, %2;" : "=f"(lo), "=f"(hi) : "l"(v));
    return lo + hi;
}

// ---------------------------------------------------------------------------
// Kernel 1: weight-norm the 4 matrices (packed layout) + rel-position tables
// ---------------------------------------------------------------------------
__global__ void prep_kernel(const float* __restrict__ wq_v, const float* __restrict__ wq_g,
                            const float* __restrict__ wk_v, const float* __restrict__ wk_g,
                            const float* __restrict__ wv_v, const float* __restrict__ wv_g,
                            const float* __restrict__ fc_v, const float* __restrict__ fc_g,
                            const float* __restrict__ rel_k, const float* __restrict__ rel_v) {
    int blk = blockIdx.x;
    if (blk < 4) {
        const float* v; const float* g;
        switch (blk) {
            case 0: v = wq_v; g = wq_g; break;
            case 1: v = wk_v; g = wk_g; break;
            case 2: v = wv_v; g = wv_g; break;
            default: v = fc_v; g = fc_g; break;
        }
        int r = threadIdx.x;           // channel (row of W)
        float s = 0.f;
        for (int d = 0; d < D_; d++) { float x = v[r*D_ + d]; s += x*x; }
        float sc = g[r] * rsqrtf(s);
        for (int d2 = 0; d2 < 64; d2++) {
            g_Wkp[blk][(d2*128 + r)*2 + 0] = v[r*D_ + 2*d2 + 0] * sc;
            g_Wkp[blk][(d2*128 + r)*2 + 1] = v[r*D_ + 2*d2 + 1] * sc;
        }
    } else {
        for (int t = threadIdx.x; t < LL; t += blockDim.x) {
            int q = t / L_, k = t % L_;
            int dist = k - q;
            dist = max(-MAXREL, min(MAXREL, dist));
            int row = dist + MAXREL;
            for (int d = 0; d < DK; d++) {
                g_K2[t*DK + d] = rel_k[row*DK + d];
                g_V2[t*DK + d] = rel_v[row*DK + d];
            }
        }
    }
}

// GEMM inner: 12x128 = s_in(12x128) @ W^T using packed weights (matrix m).
// Thread tile: channels (2p, 2p+1), rows 3g..3g+2.  Writes to dst (smem or reg-consumer).
__device__ __forceinline__ void gemm_tile(const float* __restrict__ s_in, int m, int p, int g,
                                          float2 res[3]) {
    const ulonglong2* __restrict__ Wp = (const ulonglong2*)(g_Wkp[m]);
    const int r0 = 3*g;
    u64t acc00 = 0, acc01 = 0, acc10 = 0, acc11 = 0, acc20 = 0, acc21 = 0;
    const ulonglong2* __restrict__ x0 = (const ulonglong2*)(s_in + (r0+0)*D_);
    const ulonglong2* __restrict__ x1 = (const ulonglong2*)(s_in + (r0+1)*D_);
    const ulonglong2* __restrict__ x2 = (const ulonglong2*)(s_in + (r0+2)*D_);
    #pragma unroll 8
    for (int i = 0; i < 32; i++) {          // 4 d's per iter
        ulonglong2 w0 = Wp[(2*i+0)*64 + p]; // (d 4i,4i+1) x channels (2p,2p+1)
        ulonglong2 w1 = Wp[(2*i+1)*64 + p]; // (d 4i+2,4i+3)
        ulonglong2 xa = x0[i];
        acc00 = fma2(xa.x, w0.x, acc00); acc01 = fma2(xa.x, w0.y, acc01);
        acc00 = fma2(xa.y, w1.x, acc00); acc01 = fma2(xa.y, w1.y, acc01);
        ulonglong2 xb = x1[i];
        acc10 = fma2(xb.x, w0.x, acc10); acc11 = fma2(xb.x, w0.y, acc11);
        acc10 = fma2(xb.y, w1.x, acc10); acc11 = fma2(xb.y, w1.y, acc11);
        ulonglong2 xc = x2[i];
        acc20 = fma2(xc.x, w0.x, acc20); acc21 = fma2(xc.x, w0.y, acc21);
        acc20 = fma2(xc.y, w1.x, acc20); acc21 = fma2(xc.y, w1.y, acc21);
    }
    res[0] = make_float2(hsum2(acc00), hsum2(acc01));
    res[1] = make_float2(hsum2(acc10), hsum2(acc11));
    res[2] = make_float2(hsum2(acc20), hsum2(acc21));
}

// ---------------------------------------------------------------------------
// Kernel 2: fused attention per (b,n)
// ---------------------------------------------------------------------------
__global__ __launch_bounds__(256) void attn_kernel(const float* __restrict__ inQ,
                                                   const float* __restrict__ inK,
                                                   const float* __restrict__ inV,
                                                   const float* __restrict__ w1,
                                                   const float* __restrict__ w2,
                                                   float* __restrict__ attn_out) {
    __shared__ __align__(16) float s_in[L_*D_];   // input tile / ctx staging
    __shared__ __align__(16) float s_q[L_*D_];
    __shared__ __align__(16) float s_k[L_*D_];
    __shared__ __align__(16) float s_v[L_*D_];
    __shared__ float s_sc[HLL];
    __shared__ float s_at[HLL];
    __shared__ float s_at2[HLL];
    __shared__ float s_w1[H_*H_], s_w2[H_*H_];

    const int bn  = blockIdx.x;
    const int tid = threadIdx.x;
    const int p   = tid & 63;     // channel pair: 2p, 2p+1
    const int g   = tid >> 6;     // row group: rows 3g..3g+2
    const int c    = tid & 127;
    const int half = tid >> 7;

    if (tid < H_*H_) { s_w1[tid] = w1[tid]; s_w2[tid] = w2[tid]; }

    // ---- projections: Q,K,V = X @ W^T ----
    for (int m = 0; m < 3; m++) {
        const float* src = (m == 0 ? inQ : (m == 1 ? inK : inV)) + (size_t)bn * L_ * D_;
        float* dst = (m == 0 ? s_q : (m == 1 ? s_k : s_v));
        for (int i = tid; i < (L_*D_)/4; i += 256)
            ((float4*)s_in)[i] = ((const float4*)src)[i];
        __syncthreads();

        float2 res[3];
        gemm_tile(s_in, m, p, g, res);
        #pragma unroll
        for (int l = 0; l < 3; l++)
            ((float2*)(dst + (3*g + l)*D_))[p] = res[l];
        __syncthreads();
    }

    // ---- scores: s1 (QK^T per head) + s2 (rel-pos keys), scaled ----
    for (int idx = tid; idx < HLL; idx += 256) {
        int h = idx / LL, rem = idx % LL;
        int i = rem / L_, j = rem % L_;
        const float4* qi = (const float4*)(s_q + i*D_ + h*DK);
        const float4* kj = (const float4*)(s_k + j*D_ + h*DK);
        const float4* k2 = (const float4*)(g_K2 + rem*DK);
        float s = 0.f;
        #pragma unroll
        for (int d4 = 0; d4 < 4; d4++) {
            float4 q4 = qi[d4], kk = kj[d4], r4 = k2[d4];
            s += q4.x*(kk.x+r4.x) + q4.y*(kk.y+r4.y) + q4.z*(kk.z+r4.z) + q4.w*(kk.w+r4.w);
        }
        s_sc[idx] = s * 0.25f;   // 1/sqrt(16)
    }
    __syncthreads();

    // ---- cross-head mix (w1) + leaky relu ----
    for (int idx = tid; idx < HLL; idx += 256) {
        int gh = idx / LL, rem = idx % LL;
        float s = 0.f;
        #pragma unroll
        for (int h = 0; h < H_; h++) s += s_sc[h*LL + rem] * s_w1[h*H_ + gh];
        s_at[idx] = (s > 0.f) ? s : 0.2f * s;
    }
    __syncthreads();

    // ---- softmax over k (96 rows of length 12) ----
    if (tid < H_*L_) {
        float* row = s_at + tid * L_;
        float mx = row[0];
        #pragma unroll
        for (int j = 1; j < L_; j++) mx = fmaxf(mx, row[j]);
        float sum = 0.f;
        #pragma unroll
        for (int j = 0; j < L_; j++) { float e = __expf(row[j] - mx); row[j] = e; sum += e; }
        float inv = 1.f / sum;
        #pragma unroll
        for (int j = 0; j < L_; j++) row[j] *= inv;
    }
    __syncthreads();

    // ---- cross-head mix (w2) ----
    for (int idx = tid; idx < HLL; idx += 256) {
        int gh = idx / LL, rem = idx % LL;
        float s = 0.f;
        #pragma unroll
        for (int h = 0; h < H_; h++) s += s_at[h*LL + rem] * s_w2[h*H_ + gh];
        s_at2[idx] = s;
    }
    __syncthreads();

    // ---- attn_ret[q, (bn*H + h), k] ----
    for (int idx = tid; idx < HLL; idx += 256) {
        int h = idx / LL, rem = idx % LL;
        int i = rem / L_, j = rem % L_;
        attn_out[(size_t)i * ((size_t)BN*H_*L_) + ((size_t)bn*H_ + h)*L_ + j] = s_at2[idx];
    }

    // ---- context: c1 (attn @ V) + c2 (attn @ rel-pos V) ----
    const int hh = c >> 4, dd = c & 15;
    float accc[6];
    #pragma unroll
    for (int l = 0; l < 6; l++) accc[l] = 0.f;
    #pragma unroll
    for (int j = 0; j < L_; j++) {
        float vj = s_v[j*D_ + c];
        #pragma unroll
        for (int l = 0; l < 6; l++) {
            int i = half*6 + l;
            accc[l] += s_at2[hh*LL + i*L_ + j] * (vj + g_V2[(i*L_ + j)*DK + dd]);
        }
    }
    float* ctxp = g_ctx + (size_t)bn * L_ * D_;
    #pragma unroll
    for (int l = 0; l < 6; l++) {
        s_in[(half*6 + l)*D_ + c] = accc[l];    // stage for per-channel stats
        ctxp[(half*6 + l)*D_ + c] = accc[l];
    }
    __syncthreads();

    // ---- per-channel BN partial sums (deterministic, no atomics) ----
    if (tid < D_) {
        float s = 0.f, ss = 0.f;
        #pragma unroll
        for (int i = 0; i < L_; i++) { float x = s_in[i*D_ + tid]; s += x; ss += x*x; }
        g_psum[tid*BN + bn]   = s;
        g_psumsq[tid*BN + bn] = ss;
    }
}

// ---------------------------------------------------------------------------
// Kernel 3: finalize BN stats (one block per channel, fixed reduction order)
// ---------------------------------------------------------------------------
__global__ void stats_kernel(const float* __restrict__ gamma, const float* __restrict__ beta) {
    const int c = blockIdx.x;
    __shared__ float sh[256], shq[256];
    float s = 0.f, ss = 0.f;
    for (int t = threadIdx.x; t < BN; t += 256) {
        s  += g_psum[c*BN + t];
        ss += g_psumsq[c*BN + t];
    }
    sh[threadIdx.x] = s; shq[threadIdx.x] = ss;
    __syncthreads();
    for (int st = 128; st > 0; st >>= 1) {
        if (threadIdx.x < st) {
            sh[threadIdx.x]  += sh[threadIdx.x + st];
            shq[threadIdx.x] += shq[threadIdx.x + st];
        }
        __syncthreads();
    }
    if (threadIdx.x == 0) {
        const float invN = 1.f / (float)ROWS;
        float mean = sh[0] * invN;
        float var  = shq[0] * invN - mean*mean;
        float sc = rsqrtf(var + 1e-5f) * gamma[c];
        g_scale[c] = sc;
        g_shift[c] = beta[c] - mean * sc;
    }
}

// ---------------------------------------------------------------------------
// Kernel 4: BN-apply + fc GEMM + ReLU + residual
// ---------------------------------------------------------------------------
__global__ __launch_bounds__(256) void out_kernel(const float* __restrict__ inV,
                                                  float* __restrict__ out) {
    __shared__ __align__(16) float s_x[L_*D_];
    __shared__ float s_scale[D_], s_shift[D_];
    const int bn  = blockIdx.x;
    const int tid = threadIdx.x;
    const int p   = tid & 63;
    const int g   = tid >> 6;

    if (tid < D_) { s_scale[tid] = g_scale[tid]; s_shift[tid] = g_shift[tid]; }
    __syncthreads();

    const float* ctxp = g_ctx + (size_t)bn * L_ * D_;
    for (int i = tid; i < L_*D_; i += 256) {
        int cc = i & 127;
        s_x[i] = ctxp[i] * s_scale[cc] + s_shift[cc];
    }
    __syncthreads();

    float2 res[3];
    gemm_tile(s_x, 3, p, g, res);

    const float2* vrow = (const float2*)(inV + (size_t)bn * L_ * D_);
    float2* orow = (float2*)(out + (size_t)bn * L_ * D_);
    #pragma unroll
    for (int l = 0; l < 3; l++) {
        int row = 3*g + l;
        float2 v = vrow[row*64 + p];
        float2 r;
        r.x = fmaxf(res[l].x, 0.f) + v.x;
        r.y = fmaxf(res[l].y, 0.f) + v.y;
        orow[row*64 + p] = r;
    }
}

// ---------------------------------------------------------------------------
extern "C" void kernel_launch(void* const* d_in, const int* in_sizes, int n_in,
                              void* d_out, int out_size) {
    const float* inQ   = (const float*)d_in[0];
    const float* inK   = (const float*)d_in[1];
    const float* inV   = (const float*)d_in[2];
    const float* wq_v  = (const float*)d_in[3];
    const float* wq_g  = (const float*)d_in[4];
    const float* wk_v  = (const float*)d_in[5];
    const float* wk_g  = (const float*)d_in[6];
    const float* wv_v  = (const float*)d_in[7];
    const float* wv_g  = (const float*)d_in[8];
    const float* fc_v  = (const float*)d_in[9];
    const float* fc_g  = (const float*)d_in[10];
    const float* rel_k = (const float*)d_in[11];
    const float* rel_v = (const float*)d_in[12];
    const float* w1    = (const float*)d_in[13];
    const float* w2    = (const float*)d_in[14];
    const float* gamma = (const float*)d_in[15];
    const float* beta  = (const float*)d_in[16];

    float* out      = (float*)d_out;
    float* attn_out = out + (size_t)ROWS * D_;   // second tuple element

    prep_kernel<<<5, 128>>>(wq_v, wq_g, wk_v, wk_g, wv_v, wv_g, fc_v, fc_g, rel_k, rel_v);
    attn_kernel<<<BN, 256>>>(inQ, inK, inV, w1, w2, attn_out);
    stats_kernel<<<D_, 256>>>(gamma, beta);
    out_kernel<<<BN, 256>>>(inV, out);
}